// round 4
// baseline (speedup 1.0000x reference)
#include <cuda_runtime.h>
#include <cstdint>
#include <cstddef>

// out[b,t,k,n,o] = sum_i x[b,t,n,i] * Wqkv[k, perm[phase,k,n], i, o]
// (invperm[perm] cancels). 64 GEMMs of [2048,1024]x[1024,192] fp32.
// sm_100 baseline target (no tcgen05 at plain sm_100): tf32 mma.sync.m16n8k8
// with cvt.rna rounding, cp.async double-buffered staging.
//
// NOTE: reference does .astype(jnp.int64) but under default JAX config that
// silently yields int32. We sniff the dtype on-device (odd 32-bit words of an
// int64 little-endian array of values <16 are all zero; an int32 permutation
// of 0..15 has at most one zero among words 1,3,5) and mask pm to [0,16).

namespace {

constexpr int N_ = 16, IN_ = 1024, K_ = 4, D3_ = 192;
constexpr int M_TOTAL = 2048;
constexpr int TILE_M = 128;
constexpr int KC = 64;                    // K per chunk
constexpr int NCHUNK = IN_ / KC;          // 16
constexpr int ROWSTR = N_ * IN_;          // 16384 floats

// smem stage layout (bytes): A tile [128 m][64 i] f32, B tile [64 i][192 o] f32
constexpr int A_STRIDE = 272;             // 256 + 16 pad
constexpr int B_STRIDE = 800;             // 768 + 32 pad
constexpr int A_BYTES  = TILE_M * A_STRIDE;   // 34816
constexpr int B_BYTES  = KC * B_STRIDE;       // 51200
constexpr int STAGE_SZ = A_BYTES + B_BYTES;   // 86016
constexpr int SMEM_TOTAL = 2 * STAGE_SZ;      // 172032 (< 227KB opt-in cap)

__device__ __forceinline__ uint32_t smem_u32(const void* p) {
    uint32_t a;
    asm("{ .reg .u64 t; cvta.to.shared.u64 t, %1; cvt.u32.u64 %0, t; }"
        : "=r"(a) : "l"(p));
    return a;
}

__device__ __forceinline__ void cp16(uint32_t dst, const void* src) {
    asm volatile("cp.async.cg.shared.global [%0], [%1], 16;"
                 :: "r"(dst), "l"(src) : "memory");
}
__device__ __forceinline__ void cp_commit() {
    asm volatile("cp.async.commit_group;" ::: "memory");
}
template <int N>
__device__ __forceinline__ void cp_wait() {
    asm volatile("cp.async.wait_group %0;" :: "n"(N) : "memory");
}

__device__ __forceinline__ uint32_t f2tf32(float f) {
    uint32_t r;
    asm("cvt.rna.tf32.f32 %0, %1;" : "=r"(r) : "f"(f));
    return r;
}

__device__ __forceinline__ void mma_tf32(float* d,
                                         uint32_t a0, uint32_t a1,
                                         uint32_t a2, uint32_t a3,
                                         uint32_t b0, uint32_t b1) {
    asm volatile(
        "mma.sync.aligned.m16n8k8.row.col.f32.tf32.tf32.f32 "
        "{%0,%1,%2,%3}, {%4,%5,%6,%7}, {%8,%9}, {%0,%1,%2,%3};"
        : "+f"(d[0]), "+f"(d[1]), "+f"(d[2]), "+f"(d[3])
        : "r"(a0), "r"(a1), "r"(a2), "r"(a3), "r"(b0), "r"(b1));
}

} // namespace

__global__ void __launch_bounds__(256, 1)
qkv_tf32_kernel(const float* __restrict__ x, const float* __restrict__ W,
                const int* __restrict__ perm32,
                const int* __restrict__ phase_p,
                float* __restrict__ out)
{
    extern __shared__ char sm[];
    const uint32_t smb = smem_u32(sm);
    const int tid = threadIdx.x;
    const int wid = tid >> 5;
    const int lid = tid & 31;
    const int gid = lid >> 2;               // groupID 0..7
    const int tg  = lid & 3;                // threadID_in_group 0..3

    const int tile_m = blockIdx.x;          // 0..15
    const int pair   = blockIdx.y;          // 0..63
    const int n = pair >> 2;
    const int k = pair & 3;
    const int m0 = tile_m * TILE_M;

    // ---- dtype-robust perm read ----
    // phase value is 0; low 32-bit word is correct for int32 or int64 LE.
    const int phase = __ldg(phase_p) & 0xFFFF;   // paranoid mask (valid values 0..P-1)
    const bool is64 = (__ldg(perm32 + 1) == 0) &&
                      (__ldg(perm32 + 3) == 0) &&
                      (__ldg(perm32 + 5) == 0);
    const int pidx = phase * (K_ * N_) + k * N_ + n;
    int pm = __ldg(perm32 + (is64 ? 2 * pidx : pidx));
    pm &= 15;                                // hard guard: keep Wb in bounds

    const float* __restrict__ Wb =
        W + ((size_t)k * N_ + (size_t)pm) * (size_t)(IN_ * D3_);
    const float* __restrict__ Xb =
        x + (size_t)n * IN_ + (size_t)m0 * ROWSTR;

    // warp grid 2 (m) x 4 (n): warp tile 64 x 48
    const int wm = wid >> 2;                // 0..1
    const int wn = wid & 3;                 // 0..3
    const int m_base = wm * 64;
    const int n_base = wn * 48;

    float acc[4][6][4];
    #pragma unroll
    for (int mt = 0; mt < 4; ++mt)
        #pragma unroll
        for (int nt = 0; nt < 6; ++nt)
            #pragma unroll
            for (int r = 0; r < 4; ++r) acc[mt][nt][r] = 0.0f;

    // ---- staging: chunk c into stage s ----
    auto load_chunk = [&](int c, int s) {
        const int kk = c * KC;
        const uint32_t sa = smb + s * STAGE_SZ;
        const uint32_t sb = sa + A_BYTES;
        // A: 128 rows x 256B  -> 2048 x 16B units, 8 per thread
        #pragma unroll
        for (int it = 0; it < 8; ++it) {
            const int e = tid + it * 256;
            const int row = e >> 4;
            const int u = e & 15;
            cp16(sa + row * A_STRIDE + u * 16,
                 Xb + (size_t)row * ROWSTR + kk + u * 4);
        }
        // B: 64 i-rows x 768B -> 3072 x 16B units, 12 per thread
        #pragma unroll
        for (int it = 0; it < 12; ++it) {
            const int e = tid + it * 256;
            const int i = e / 48;
            const int u = e - i * 48;
            cp16(sb + i * B_STRIDE + u * 16,
                 Wb + (size_t)(kk + i) * D3_ + u * 4);
        }
    };

    load_chunk(0, 0);
    cp_commit();

    for (int c = 0; c < NCHUNK; ++c) {
        const int s = c & 1;
        if (c + 1 < NCHUNK) {
            load_chunk(c + 1, s ^ 1);
            cp_commit();
            cp_wait<1>();
        } else {
            cp_wait<0>();
        }
        __syncthreads();

        const char* sa = sm + s * STAGE_SZ;
        const char* sb = sa + A_BYTES;
        // hoist per-warp row bases so the ks-loop only adds small offsets
        const char* sa_r0 = sa + (m_base + gid) * A_STRIDE;
        const char* sb_c  = sb + (n_base + gid) * 4;

        #pragma unroll
        for (int ks = 0; ks < 8; ++ks) {
            const int i0 = ks * 8 + tg;
            // A fragments: 4 m-tiles x 4 regs
            uint32_t af[4][4];
            #pragma unroll
            for (int mt = 0; mt < 4; ++mt) {
                const char* p = sa_r0 + mt * 16 * A_STRIDE + i0 * 4;
                af[mt][0] = f2tf32(*(const float*)(p));
                af[mt][1] = f2tf32(*(const float*)(p + 8 * A_STRIDE));
                af[mt][2] = f2tf32(*(const float*)(p + 16));
                af[mt][3] = f2tf32(*(const float*)(p + 8 * A_STRIDE + 16));
            }
            #pragma unroll
            for (int nt = 0; nt < 6; ++nt) {
                const char* q = sb_c + i0 * B_STRIDE + nt * 32;
                const uint32_t b0 = f2tf32(*(const float*)(q));
                const uint32_t b1 = f2tf32(*(const float*)(q + 4 * B_STRIDE));
                #pragma unroll
                for (int mt = 0; mt < 4; ++mt)
                    mma_tf32(acc[mt][nt],
                             af[mt][0], af[mt][1], af[mt][2], af[mt][3], b0, b1);
            }
        }
        __syncthreads();
    }

    // ---- epilogue: acc -> out ----
    // row r = m0 + m_base + mt*16 + gid (+8), col = n_base + nt*8 + tg*2 (+1)
    #pragma unroll
    for (int mt = 0; mt < 4; ++mt) {
        const size_t r0 = (size_t)(m0 + m_base + mt * 16 + gid);
        const size_t r1 = r0 + 8;
        float* ob0 = out + (((r0 * K_ + (size_t)k) * N_) + (size_t)n) * (size_t)D3_;
        float* ob1 = out + (((r1 * K_ + (size_t)k) * N_) + (size_t)n) * (size_t)D3_;
        #pragma unroll
        for (int nt = 0; nt < 6; ++nt) {
            const int col = n_base + nt * 8 + tg * 2;
            *(float2*)(ob0 + col) = make_float2(acc[mt][nt][0], acc[mt][nt][1]);
            *(float2*)(ob1 + col) = make_float2(acc[mt][nt][2], acc[mt][nt][3]);
        }
    }
}

extern "C" void kernel_launch(void* const* d_in, const int* in_sizes, int n_in,
                              void* d_out, int out_size) {
    const float* x     = (const float*)d_in[0];
    const float* Wqkv  = (const float*)d_in[1];
    const int* perm32  = (const int*)d_in[2];      // int32 OR int64 (sniffed on device)
    // d_in[3] = invperm (unused: invperm[perm[.]] == identity cancels)
    const int* phase   = (const int*)d_in[4];      // value 0; low word valid i32/i64
    float* out         = (float*)d_out;

    cudaFuncSetAttribute(qkv_tf32_kernel,
                         cudaFuncAttributeMaxDynamicSharedMemorySize, SMEM_TOTAL);
    dim3 grid(M_TOTAL / TILE_M, K_ * N_);   // (16, 64)
    qkv_tf32_kernel<<<grid, 256, SMEM_TOTAL>>>(x, Wqkv, perm32, phase, out);
}